// round 2
// baseline (speedup 1.0000x reference)
#include <cuda_runtime.h>
#include <cuda_bf16.h>

#define NMAX   50000
#define FEAT   128
#define HID    64
#define NCLS   16

// ---- device scratch (no allocations allowed) ----
__device__ float g_deg [NMAX];
__device__ float g_dinv[NMAX];
__device__ float g_bufA[(size_t)NMAX * HID];
__device__ float g_bufB[(size_t)NMAX * HID];
__device__ int   g_is64;

__device__ __forceinline__ float* bufptr(int sel) { return sel ? g_bufB : g_bufA; }

// Detect whether edge_index is int64 or int32: if interpreted as int64 all
// sampled values are valid node ids, it's int64; int32 data read as int64
// packs two ids per word -> huge values.
__global__ void k_detect(const void* __restrict__ idx) {
    if (threadIdx.x == 0 && blockIdx.x == 0) {
        const long long* p = (const long long*)idx;
        int ok = 1;
        for (int i = 0; i < 1024; i++) {
            long long v = p[i];
            if (v < 0 || v >= NMAX) { ok = 0; break; }
        }
        g_is64 = ok;
    }
}

__device__ __forceinline__ int edge_at(const void* __restrict__ idx, long long i) {
    if (g_is64) return (int)((const long long*)idx)[i];
    return ((const int*)idx)[i];
}

// ---- degree / norm ----
__global__ void k_deg_init(int n) {
    int i = blockIdx.x * blockDim.x + threadIdx.x;
    if (i < n) g_deg[i] = 1.0f;   // self-loop
}

__global__ void k_deg_edges(const void* __restrict__ idx, long long E) {
    long long e = (long long)blockIdx.x * blockDim.x + threadIdx.x;
    if (e < E) {
        int d = edge_at(idx, E + e);
        atomicAdd(&g_deg[d], 1.0f);
    }
}

__global__ void k_dinv(int n) {
    int i = blockIdx.x * blockDim.x + threadIdx.x;
    if (i < n) g_dinv[i] = rsqrtf(g_deg[i]);
}

// ---- GEMM: [n,K] @ [K,64] -> 64-wide rows.  in_sel<0 means read Aext. ----
template<int K>
__global__ void k_gemm(const float* __restrict__ Aext, int in_sel, int out_sel,
                       const float* __restrict__ W, int n) {
    __shared__ float sW[K * HID];
    __shared__ float sx[4 * K];
    const float* A = (in_sel < 0) ? Aext : bufptr(in_sel);
    float* O = bufptr(out_sel);
    int t = threadIdx.x;                 // 256 threads
    for (int i = t; i < K * HID; i += 256) sW[i] = W[i];
    int node0 = blockIdx.x * 32;
    int col = t & 63, q = t >> 6;        // q in 0..3
    for (int tile = 0; tile < 32; tile += 4) {
        __syncthreads();
        for (int i = t; i < 4 * K; i += 256) {
            int r = i / K, k = i % K;
            int node = node0 + tile + r;
            sx[i] = (node < n) ? A[(size_t)node * K + k] : 0.0f;
        }
        __syncthreads();
        float acc = 0.0f;
        #pragma unroll 8
        for (int k = 0; k < K; k++)
            acc += sx[q * K + k] * sW[k * HID + col];
        int node = node0 + tile + q;
        if (node < n) O[(size_t)node * HID + col] = acc;
    }
}

// ---- self-loop init: out = in * dinv[node]^2 ----
__global__ void k_selfinit(int in_sel, int out_sel, int n) {
    long long idx = (long long)blockIdx.x * blockDim.x + threadIdx.x;
    if (idx < (long long)n * HID) {
        int node = (int)(idx >> 6);
        float dv = g_dinv[node];
        bufptr(out_sel)[idx] = bufptr(in_sel)[idx] * dv * dv;
    }
}

// ---- edge scatter: half-warp per edge, float4 vector RED ----
__global__ void k_scatter(const void* __restrict__ idx, long long E,
                          int in_sel, int out_sel) {
    long long hw = (long long)blockIdx.x * 16 + (threadIdx.x >> 4);
    if (hw >= E) return;
    int i = threadIdx.x & 15;
    int s = edge_at(idx, hw);
    int d = edge_at(idx, E + hw);
    float norm = g_dinv[s] * g_dinv[d];
    const float4* hs = (const float4*)(bufptr(in_sel) + (size_t)s * HID);
    float4 v = hs[i];
    float* hd = bufptr(out_sel) + (size_t)d * HID + i * 4;
    asm volatile("red.global.add.v4.f32 [%0], {%1,%2,%3,%4};"
                 :: "l"(hd), "f"(v.x * norm), "f"(v.y * norm),
                    "f"(v.z * norm), "f"(v.w * norm) : "memory");
}

// ---- bias + relu ----
__global__ void k_bias_relu(int in_sel, int out_sel, const float* __restrict__ b, int n) {
    long long idx = (long long)blockIdx.x * blockDim.x + threadIdx.x;
    if (idx < (long long)n * HID) {
        int f = (int)(idx & 63);
        bufptr(out_sel)[idx] = fmaxf(bufptr(in_sel)[idx] + b[f], 0.0f);
    }
}

// ---- output head: logits = h @ Wout + bout, softmax over 16 classes ----
__global__ void k_out(int in_sel, const float* __restrict__ Wout,
                      const float* __restrict__ bout, float* __restrict__ out, int n) {
    __shared__ float sW[HID * NCLS];
    int t = threadIdx.y * 16 + threadIdx.x;   // 256 threads
    for (int i = t; i < HID * NCLS; i += 256) sW[i] = Wout[i];
    __syncthreads();
    int node = blockIdx.x * 16 + threadIdx.y;
    if (node >= n) return;
    int c = threadIdx.x;                      // class 0..15
    const float* hr = bufptr(in_sel) + (size_t)node * HID;
    float acc = bout[c];
    #pragma unroll
    for (int k = 0; k < HID; k++)
        acc += hr[k] * sW[k * NCLS + c];
    // softmax across the 16 lanes of this half-warp
    float m = acc;
    #pragma unroll
    for (int o = 8; o; o >>= 1) m = fmaxf(m, __shfl_xor_sync(0xffffffffu, m, o, 16));
    float e = __expf(acc - m);
    float s = e;
    #pragma unroll
    for (int o = 8; o; o >>= 1) s += __shfl_xor_sync(0xffffffffu, s, o, 16);
    out[(size_t)node * NCLS + c] = e / s;
}

extern "C" void kernel_launch(void* const* d_in, const int* in_sizes, int n_in,
                              void* d_out, int out_size) {
    const float* x    = (const float*)d_in[0];
    const void*  ei   = d_in[1];
    const float* W1   = (const float*)d_in[2];
    const float* b1   = (const float*)d_in[3];
    const float* W2   = (const float*)d_in[4];
    const float* b2   = (const float*)d_in[5];
    const float* Wout = (const float*)d_in[6];
    const float* bout = (const float*)d_in[7];
    float* out = (float*)d_out;

    int       n = in_sizes[0] / FEAT;
    long long E = (long long)in_sizes[1] / 2;

    int nb_n   = (n + 255) / 256;
    int nb_nh  = (int)(((long long)n * HID + 255) / 256);
    int nb_e   = (int)((E + 255) / 256);
    int nb_sc  = (int)((E + 15) / 16);       // 16 edges per 256-thread block
    int nb_gm  = (n + 31) / 32;

    k_detect<<<1, 32>>>(ei);
    k_deg_init<<<nb_n, 256>>>(n);
    k_deg_edges<<<nb_e, 256>>>(ei, E);
    k_dinv<<<nb_n, 256>>>(n);

    // layer 1: A = x@W1 -> bufA ; agg -> bufB ; relu -> bufA (h1)
    k_gemm<FEAT><<<nb_gm, 256>>>(x, -1, 0, W1, n);
    k_selfinit<<<nb_nh, 256>>>(0, 1, n);
    k_scatter<<<nb_sc, 256>>>(ei, E, 0, 1);
    k_bias_relu<<<nb_nh, 256>>>(1, 0, b1, n);

    // layer 2: h1@W2 -> bufB ; agg -> bufA ; relu -> bufB (h2)
    k_gemm<HID><<<nb_gm, 256>>>(nullptr, 0, 1, W2, n);
    k_selfinit<<<nb_nh, 256>>>(1, 0, n);
    k_scatter<<<nb_sc, 256>>>(ei, E, 1, 0);
    k_bias_relu<<<nb_nh, 256>>>(0, 1, b2, n);

    // head
    dim3 blk(16, 16);
    k_out<<<(n + 15) / 16, blk>>>(1, Wout, bout, out, n);
}

// round 4
// speedup vs baseline: 1.2273x; 1.2273x over previous
#include <cuda_runtime.h>
#include <cuda_bf16.h>

#define NMAX   50000
#define EMAX   800000
#define FEAT   128
#define HID    64
#define NCLS   16

// ---- device scratch (no allocations allowed) ----
__device__ int   g_cnt [NMAX];
__device__ float g_dinv[NMAX];
__device__ int   g_src [EMAX];
__device__ int   g_dst [EMAX];
__device__ float g_norm[EMAX];
__device__ float g_bufA[(size_t)NMAX * HID];
__device__ float g_bufB[(size_t)NMAX * HID];
__device__ int   g_is64;

__device__ __forceinline__ float* bufptr(int sel) { return sel ? g_bufB : g_bufA; }

__device__ __forceinline__ int edge_at(const void* __restrict__ idx, long long i) {
    if (g_is64) return (int)((const long long*)idx)[i];
    return ((const int*)idx)[i];
}

// ---- prep: zero degree counts; block 0 detects index dtype in parallel ----
__global__ void k_prep(const void* __restrict__ idx, int n) {
    int i = blockIdx.x * 256 + threadIdx.x;
    if (i < n) g_cnt[i] = 0;
    if (blockIdx.x == 0) {
        __shared__ int sok[8];
        int ok = 1;
        #pragma unroll
        for (int j = 0; j < 4; j++) {
            long long v = ((const long long*)idx)[threadIdx.x * 4 + j];
            if (v < 0 || v >= n) ok = 0;
        }
        unsigned m = __ballot_sync(0xffffffffu, ok);
        if ((threadIdx.x & 31) == 0) sok[threadIdx.x >> 5] = (m == 0xffffffffu);
        __syncthreads();
        if (threadIdx.x == 0) {
            int all = 1;
            #pragma unroll
            for (int w = 0; w < 8; w++) all &= sok[w];
            g_is64 = all;
        }
    }
}

// ---- convert indices to int32 + count in-degrees ----
__global__ void k_cvt_deg(const void* __restrict__ idx, long long E) {
    long long e = (long long)blockIdx.x * 256 + threadIdx.x;
    if (e >= E) return;
    int s = edge_at(idx, e);
    int d = edge_at(idx, E + e);
    g_src[e] = s;
    g_dst[e] = d;
    atomicAdd(&g_cnt[d], 1);
}

__global__ void k_dinv(int n) {
    int i = blockIdx.x * 256 + threadIdx.x;
    if (i < n) g_dinv[i] = rsqrtf((float)g_cnt[i] + 1.0f);   // +1 self-loop
}

// ---- GEMM: [n,K] @ [K,64]; optional fused bias+relu on input load;
//      dual output: raw (for edge gathers) + raw*dinv^2 (scatter accumulator init)
template<int K, bool RELU_IN>
__global__ void k_gemm(const float* __restrict__ Aext, int in_sel,
                       const float* __restrict__ bin,
                       int raw_sel, int init_sel,
                       const float* __restrict__ W, int n) {
    __shared__ float sW[K * HID];
    __shared__ float sx[4 * K];
    const float* A = (in_sel < 0) ? Aext : bufptr(in_sel);
    float* Oraw  = bufptr(raw_sel);
    float* Oinit = bufptr(init_sel);
    int t = threadIdx.x;                       // 256 threads
    for (int i = t; i < K * HID / 4; i += 256)
        ((float4*)sW)[i] = ((const float4*)W)[i];
    int node0 = blockIdx.x * 32;
    int col = t & 63, q = t >> 6;              // q in 0..3
    for (int tile = 0; tile < 32; tile += 4) {
        __syncthreads();
        for (int i = t; i < K; i += 256) {     // 4 rows * K/4 float4
            int r = i / (K / 4), k = i % (K / 4);
            int node = node0 + tile + r;
            float4 v = make_float4(0.f, 0.f, 0.f, 0.f);
            if (node < n) v = ((const float4*)(A + (size_t)node * K))[k];
            if (RELU_IN) {
                float4 b = ((const float4*)bin)[k];
                v.x = fmaxf(v.x + b.x, 0.f); v.y = fmaxf(v.y + b.y, 0.f);
                v.z = fmaxf(v.z + b.z, 0.f); v.w = fmaxf(v.w + b.w, 0.f);
            }
            ((float4*)(sx + r * K))[k] = v;
        }
        __syncthreads();
        float acc = 0.0f;
        #pragma unroll
        for (int k = 0; k < K; k++)
            acc += sx[q * K + k] * sW[k * HID + col];
        int node = node0 + tile + q;
        if (node < n) {
            Oraw[(size_t)node * HID + col] = acc;
            float dv = g_dinv[node];
            Oinit[(size_t)node * HID + col] = acc * dv * dv;
        }
    }
}

// ---- edge scatter: half-warp per edge, float4 vector RED.
//      FIRST=true computes & caches per-edge norm; else reuses it.
template<bool FIRST>
__global__ void k_scatter(long long E, int in_sel, int out_sel) {
    long long hw = (long long)blockIdx.x * 16 + (threadIdx.x >> 4);
    if (hw >= E) return;
    const float* src_feat = bufptr(in_sel);
    float* dst_feat = bufptr(out_sel);
    int i = threadIdx.x & 15;
    int s = g_src[hw], d = g_dst[hw];
    float norm;
    if (FIRST) {
        norm = g_dinv[s] * g_dinv[d];
        if (i == 0) g_norm[hw] = norm;
    } else {
        norm = g_norm[hw];
    }
    float4 v = ((const float4*)(src_feat + (size_t)s * HID))[i];
    float* hd = dst_feat + (size_t)d * HID + i * 4;
    asm volatile("red.global.add.v4.f32 [%0], {%1,%2,%3,%4};"
                 :: "l"(hd), "f"(v.x * norm), "f"(v.y * norm),
                    "f"(v.z * norm), "f"(v.w * norm) : "memory");
}

// ---- output head: relu(h+b2) @ Wout + bout, softmax over 16 classes ----
__global__ void k_out(int in_sel, const float* __restrict__ b2,
                      const float* __restrict__ Wout, const float* __restrict__ bout,
                      float* __restrict__ out, int n) {
    __shared__ float sW[HID * NCLS];
    __shared__ float sh[16 * HID];
    const float* H = bufptr(in_sel);
    int t = threadIdx.x;                       // 256 threads
    {
        int i = t;                             // HID*NCLS/4 == 256
        ((float4*)sW)[i] = ((const float4*)Wout)[i];
    }
    int node0 = blockIdx.x * 16;
    {
        int i = t;                             // 16*HID/4 == 256
        int r = i / (HID / 4), k = i % (HID / 4);
        int node = node0 + r;
        float4 v = make_float4(0.f, 0.f, 0.f, 0.f);
        if (node < n) v = ((const float4*)(H + (size_t)node * HID))[k];
        float4 b = ((const float4*)b2)[k];
        v.x = fmaxf(v.x + b.x, 0.f); v.y = fmaxf(v.y + b.y, 0.f);
        v.z = fmaxf(v.z + b.z, 0.f); v.w = fmaxf(v.w + b.w, 0.f);
        ((float4*)(sh + r * HID))[k] = v;
    }
    __syncthreads();
    int node = node0 + (t >> 4);
    if (node >= n) return;
    int c = t & 15;
    const float* hr = sh + (t >> 4) * HID;
    float acc = bout[c];
    #pragma unroll
    for (int k = 0; k < HID; k++)
        acc += hr[k] * sW[k * NCLS + c];
    float m = acc;
    #pragma unroll
    for (int o = 8; o; o >>= 1) m = fmaxf(m, __shfl_xor_sync(0xffffffffu, m, o, 16));
    float e = __expf(acc - m);
    float s = e;
    #pragma unroll
    for (int o = 8; o; o >>= 1) s += __shfl_xor_sync(0xffffffffu, s, o, 16);
    out[(size_t)node * NCLS + c] = e / s;
}

extern "C" void kernel_launch(void* const* d_in, const int* in_sizes, int n_in,
                              void* d_out, int out_size) {
    const float* x    = (const float*)d_in[0];
    const void*  ei   = d_in[1];
    const float* W1   = (const float*)d_in[2];
    const float* b1   = (const float*)d_in[3];
    const float* W2   = (const float*)d_in[4];
    const float* b2   = (const float*)d_in[5];
    const float* Wout = (const float*)d_in[6];
    const float* bout = (const float*)d_in[7];
    float* out = (float*)d_out;

    int       n = in_sizes[0] / FEAT;
    long long E = (long long)in_sizes[1] / 2;

    int nb_n  = (n + 255) / 256;
    int nb_e  = (int)((E + 255) / 256);
    int nb_sc = (int)((E + 15) / 16);
    int nb_gm = (n + 31) / 32;

    k_prep<<<nb_n, 256>>>(ei, n);
    k_cvt_deg<<<nb_e, 256>>>(ei, E);
    k_dinv<<<nb_n, 256>>>(n);

    // layer 1: raw = x@W1 -> bufA(0) ; init -> bufB(1) ; scatter A->B
    k_gemm<FEAT, false><<<nb_gm, 256>>>(x, -1, nullptr, 0, 1, W1, n);
    k_scatter<true><<<nb_sc, 256>>>(E, 0, 1);

    // layer 2: input relu(bufB+b1); raw -> bufA(0) ; init -> bufB(1, in-place safe) ; scatter
    k_gemm<HID, true><<<nb_gm, 256>>>(nullptr, 1, b1, 0, 1, W2, n);
    k_scatter<false><<<nb_sc, 256>>>(E, 0, 1);

    // head: relu(bufB+b2) @ Wout + bout, softmax
    k_out<<<(n + 15) / 16, 256>>>(1, b2, Wout, bout, out, n);
}

// round 5
// speedup vs baseline: 1.8275x; 1.4890x over previous
#include <cuda_runtime.h>
#include <cuda_bf16.h>

#define NMAX   50000
#define EMAX   800000
#define FEAT   128
#define HID    64
#define NCLS   16

// ---- device scratch (no allocations allowed) ----
__device__ int   g_cnt [NMAX];
__device__ float g_dinv[NMAX];
__device__ int   g_src [EMAX];
__device__ int   g_dst [EMAX];
__device__ float g_norm[EMAX];
__device__ float g_bufA[(size_t)NMAX * HID];
__device__ float g_bufB[(size_t)NMAX * HID];
__device__ int   g_is64;

__device__ __forceinline__ float* bufptr(int sel) { return sel ? g_bufB : g_bufA; }

__device__ __forceinline__ int edge_at(const void* __restrict__ idx, long long i) {
    if (g_is64) return (int)((const long long*)idx)[i];
    return ((const int*)idx)[i];
}

// ---- prep: zero degree counts; block 0 detects index dtype in parallel ----
__global__ void k_prep(const void* __restrict__ idx, int n) {
    int i = blockIdx.x * 256 + threadIdx.x;
    if (i < n) g_cnt[i] = 0;
    if (blockIdx.x == 0) {
        __shared__ int sok[8];
        int ok = 1;
        #pragma unroll
        for (int j = 0; j < 4; j++) {
            long long v = ((const long long*)idx)[threadIdx.x * 4 + j];
            if (v < 0 || v >= n) ok = 0;
        }
        unsigned m = __ballot_sync(0xffffffffu, ok);
        if ((threadIdx.x & 31) == 0) sok[threadIdx.x >> 5] = (m == 0xffffffffu);
        __syncthreads();
        if (threadIdx.x == 0) {
            int all = 1;
            #pragma unroll
            for (int w = 0; w < 8; w++) all &= sok[w];
            g_is64 = all;
        }
    }
}

// ---- convert indices to int32 + count in-degrees ----
__global__ void k_cvt_deg(const void* __restrict__ idx, long long E) {
    long long e = (long long)blockIdx.x * 256 + threadIdx.x;
    if (e >= E) return;
    int s = edge_at(idx, e);
    int d = edge_at(idx, E + e);
    g_src[e] = s;
    g_dst[e] = d;
    atomicAdd(&g_cnt[d], 1);
}

__global__ void k_dinv(int n) {
    int i = blockIdx.x * 256 + threadIdx.x;
    if (i < n) g_dinv[i] = rsqrtf((float)g_cnt[i] + 1.0f);   // +1 self-loop
}

// ---- register-blocked GEMM: [n,K] @ [K,64] with packed f32x2 FMA.
//      64 nodes x 64 cols per block; thread computes 4x4 tile.
//      optional fused bias+relu on input load; dual output raw + raw*dinv^2.
template<int K, bool RELU_IN>
__global__ void __launch_bounds__(256) k_gemm(
        const float* __restrict__ Aext, int in_sel,
        const float* __restrict__ bin,
        int raw_sel, int init_sel,
        const float* __restrict__ W, int n) {
    constexpr int KC = 32;                      // K-chunk
    __shared__ float sW[K * HID];               // full W
    __shared__ float sx[64 * KC];               // 64 rows x 32 k
    const float* A = (in_sel < 0) ? Aext : bufptr(in_sel);
    float* Oraw  = bufptr(raw_sel);
    float* Oinit = bufptr(init_sel);
    int t  = threadIdx.x;                       // 256 threads
    int tx = t & 15, ty = t >> 4;
    int node0 = blockIdx.x * 64;

    for (int i = t; i < K * HID / 4; i += 256)
        ((float4*)sW)[i] = ((const float4*)W)[i];

    unsigned long long acc[4][2];
    #pragma unroll
    for (int i = 0; i < 4; i++) { acc[i][0] = 0ull; acc[i][1] = 0ull; }

    const float4* Av = (const float4*)A;
    #pragma unroll
    for (int kc = 0; kc < K / KC; kc++) {
        __syncthreads();
        // stage sx chunk: 64 rows x 8 float4 = 512 float4, 2 per thread
        #pragma unroll
        for (int j = 0; j < 2; j++) {
            int i = t + j * 256;
            int r = i >> 3, kv = i & 7;
            int node = node0 + r;
            float4 v = make_float4(0.f, 0.f, 0.f, 0.f);
            if (node < n) v = Av[(size_t)node * (K / 4) + kc * (KC / 4) + kv];
            if (RELU_IN) {
                float4 b = ((const float4*)bin)[kc * (KC / 4) + kv];
                v.x = fmaxf(v.x + b.x, 0.f); v.y = fmaxf(v.y + b.y, 0.f);
                v.z = fmaxf(v.z + b.z, 0.f); v.w = fmaxf(v.w + b.w, 0.f);
            }
            ((float4*)sx)[i] = v;
        }
        __syncthreads();
        #pragma unroll
        for (int k = 0; k < KC; k++) {
            // W row k: 4 consecutive cols for this thread, as 2 packed f32x2
            ulonglong2 wv = ((const ulonglong2*)sW)[(size_t)(kc * KC + k) * 16 + tx];
            #pragma unroll
            for (int i = 0; i < 4; i++) {
                unsigned au = __float_as_uint(sx[(ty * 4 + i) * KC + k]);
                unsigned long long aa;
                asm("mov.b64 %0, {%1, %1};" : "=l"(aa) : "r"(au));
                asm("fma.rn.f32x2 %0, %1, %2, %0;" : "+l"(acc[i][0]) : "l"(aa), "l"(wv.x));
                asm("fma.rn.f32x2 %0, %1, %2, %0;" : "+l"(acc[i][1]) : "l"(aa), "l"(wv.y));
            }
        }
    }

    // epilogue: unpack, write raw + init(=raw*dinv^2)
    #pragma unroll
    for (int i = 0; i < 4; i++) {
        int node = node0 + ty * 4 + i;
        if (node >= n) break;
        unsigned lo0, hi0, lo1, hi1;
        asm("mov.b64 {%0, %1}, %2;" : "=r"(lo0), "=r"(hi0) : "l"(acc[i][0]));
        asm("mov.b64 {%0, %1}, %2;" : "=r"(lo1), "=r"(hi1) : "l"(acc[i][1]));
        float4 raw = make_float4(__uint_as_float(lo0), __uint_as_float(hi0),
                                 __uint_as_float(lo1), __uint_as_float(hi1));
        ((float4*)Oraw)[(size_t)node * (HID / 4) + tx] = raw;
        float dv = g_dinv[node];
        float s = dv * dv;
        float4 ini = make_float4(raw.x * s, raw.y * s, raw.z * s, raw.w * s);
        ((float4*)Oinit)[(size_t)node * (HID / 4) + tx] = ini;
    }
}

// ---- edge scatter: half-warp per edge, float4 vector RED.
//      FIRST=true computes & caches per-edge norm; else reuses it.
template<bool FIRST>
__global__ void k_scatter(long long E, int in_sel, int out_sel) {
    long long hw = (long long)blockIdx.x * 16 + (threadIdx.x >> 4);
    if (hw >= E) return;
    const float* src_feat = bufptr(in_sel);
    float* dst_feat = bufptr(out_sel);
    int i = threadIdx.x & 15;
    int s = g_src[hw], d = g_dst[hw];
    float norm;
    if (FIRST) {
        norm = g_dinv[s] * g_dinv[d];
        if (i == 0) g_norm[hw] = norm;
    } else {
        norm = g_norm[hw];
    }
    float4 v = ((const float4*)(src_feat + (size_t)s * HID))[i];
    float* hd = dst_feat + (size_t)d * HID + i * 4;
    asm volatile("red.global.add.v4.f32 [%0], {%1,%2,%3,%4};"
                 :: "l"(hd), "f"(v.x * norm), "f"(v.y * norm),
                    "f"(v.z * norm), "f"(v.w * norm) : "memory");
}

// ---- output head: relu(h+b2) @ Wout + bout, softmax over 16 classes ----
__global__ void k_out(int in_sel, const float* __restrict__ b2,
                      const float* __restrict__ Wout, const float* __restrict__ bout,
                      float* __restrict__ out, int n) {
    __shared__ float sW[HID * NCLS];
    __shared__ float sh[16 * HID];
    const float* H = bufptr(in_sel);
    int t = threadIdx.x;                       // 256 threads
    {
        int i = t;                             // HID*NCLS/4 == 256
        ((float4*)sW)[i] = ((const float4*)Wout)[i];
    }
    int node0 = blockIdx.x * 16;
    {
        int i = t;                             // 16*HID/4 == 256
        int r = i / (HID / 4), k = i % (HID / 4);
        int node = node0 + r;
        float4 v = make_float4(0.f, 0.f, 0.f, 0.f);
        if (node < n) v = ((const float4*)(H + (size_t)node * HID))[k];
        float4 b = ((const float4*)b2)[k];
        v.x = fmaxf(v.x + b.x, 0.f); v.y = fmaxf(v.y + b.y, 0.f);
        v.z = fmaxf(v.z + b.z, 0.f); v.w = fmaxf(v.w + b.w, 0.f);
        ((float4*)(sh + r * HID))[k] = v;
    }
    __syncthreads();
    int node = node0 + (t >> 4);
    if (node >= n) return;
    int c = t & 15;
    const float* hr = sh + (t >> 4) * HID;
    float acc = bout[c];
    #pragma unroll
    for (int k = 0; k < HID; k++)
        acc += hr[k] * sW[k * NCLS + c];
    float m = acc;
    #pragma unroll
    for (int o = 8; o; o >>= 1) m = fmaxf(m, __shfl_xor_sync(0xffffffffu, m, o, 16));
    float e = __expf(acc - m);
    float s = e;
    #pragma unroll
    for (int o = 8; o; o >>= 1) s += __shfl_xor_sync(0xffffffffu, s, o, 16);
    out[(size_t)node * NCLS + c] = e / s;
}

extern "C" void kernel_launch(void* const* d_in, const int* in_sizes, int n_in,
                              void* d_out, int out_size) {
    const float* x    = (const float*)d_in[0];
    const void*  ei   = d_in[1];
    const float* W1   = (const float*)d_in[2];
    const float* b1   = (const float*)d_in[3];
    const float* W2   = (const float*)d_in[4];
    const float* b2   = (const float*)d_in[5];
    const float* Wout = (const float*)d_in[6];
    const float* bout = (const float*)d_in[7];
    float* out = (float*)d_out;

    int       n = in_sizes[0] / FEAT;
    long long E = (long long)in_sizes[1] / 2;

    int nb_n  = (n + 255) / 256;
    int nb_e  = (int)((E + 255) / 256);
    int nb_sc = (int)((E + 15) / 16);
    int nb_gm = (n + 63) / 64;

    k_prep<<<nb_n, 256>>>(ei, n);
    k_cvt_deg<<<nb_e, 256>>>(ei, E);
    k_dinv<<<nb_n, 256>>>(n);

    // layer 1: raw = x@W1 -> bufA(0) ; init -> bufB(1) ; scatter A->B
    k_gemm<FEAT, false><<<nb_gm, 256>>>(x, -1, nullptr, 0, 1, W1, n);
    k_scatter<true><<<nb_sc, 256>>>(E, 0, 1);

    // layer 2: input relu(bufB+b1); raw -> bufA(0) ; init -> bufB(1, in-place safe) ; scatter
    k_gemm<HID, true><<<nb_gm, 256>>>(nullptr, 1, b1, 0, 1, W2, n);
    k_scatter<false><<<nb_sc, 256>>>(E, 0, 1);

    // head: relu(bufB+b2) @ Wout + bout, softmax
    k_out<<<(n + 15) / 16, 256>>>(1, b2, Wout, bout, out, n);
}